// round 17
// baseline (speedup 1.0000x reference)
#include <cuda_runtime.h>
#include <cuda_bf16.h>
#include <math.h>
#include <stdint.h>

// ---------------------------------------------------------------------------
// Problem constants
// ---------------------------------------------------------------------------
#define N_TOT 8192
#define D 128
#define TEMP_INV (1.0f/0.07f)
#define SCALE_LOG2 (1.44269504088896340736f/0.07f)   /* log2(e)/T */
#define LN2F 0.6931471805599453f
#define NCTA 608            /* 4 CTAs per SM x 152 SMs -> all co-resident */
#define NUNITS 2048         /* 64 I-blocks x 32 units (unit = 256 J cols) */
#define NSLOT 16            /* slot = cta & 15; span per I-block <= 12 */
#define FIN_BLOCKS 256

// SMEM: A = 128 rows x 128 bf16 (resident), B = 32-row subtiles, dbl-buffered.
#define PKB 272
#define A_TB (128 * PKB)        /* 34816 */
#define B_TB (32 * PKB)         /* 8704  */
#define OFF_A 0
#define OFF_B(b) (A_TB + (b)*B_TB)
#define SMEM_BYTES (A_TB + 2*B_TB)   /* 52224 -> 4 CTAs/SM guaranteed */

// ---------------------------------------------------------------------------
// Device scratch
// ---------------------------------------------------------------------------
__device__ __nv_bfloat16 g_hi[N_TOT * D];
__device__ float    g_norm[N_TOT];          /* |f_i|^2, fp32 exact */
__device__ float    g_G[2][D];
__device__ int      g_C[2];
__device__ int      g_cls[N_TOT];           /* 0 invalid, 1 class0, 2 class1 */
__device__ float2   g_pp[N_TOT][NSLOT];     /* (m,s) log2-domain partials, transposed */
__device__ float    g_bsum[FIN_BLOCKS];
__device__ int      g_fin_count;
__device__ int      g_ready;                /* phase-0 arrival counter */
__device__ int      g_is64;

// ---------------------------------------------------------------------------
// Family-safe PTX helpers
// ---------------------------------------------------------------------------
__device__ __forceinline__ uint32_t smem_u32(const void* p) {
    uint32_t a;
    asm("{ .reg .u64 t; cvta.to.shared.u64 t, %1; cvt.u32.u64 %0, t; }" : "=r"(a) : "l"(p));
    return a;
}
__device__ __forceinline__ void ldsm4(uint32_t* r, uint32_t addr) {
    asm volatile("ldmatrix.sync.aligned.m8n8.x4.shared.b16 {%0,%1,%2,%3}, [%4];"
                 : "=r"(r[0]), "=r"(r[1]), "=r"(r[2]), "=r"(r[3]) : "r"(addr));
}
__device__ __forceinline__ void mma16816(float* c, const uint32_t* a, uint32_t b0, uint32_t b1) {
    asm volatile("mma.sync.aligned.m16n8k16.row.col.f32.bf16.bf16.f32 "
                 "{%0,%1,%2,%3}, {%4,%5,%6,%7}, {%8,%9}, {%0,%1,%2,%3};"
                 : "+f"(c[0]), "+f"(c[1]), "+f"(c[2]), "+f"(c[3])
                 : "r"(a[0]), "r"(a[1]), "r"(a[2]), "r"(a[3]), "r"(b0), "r"(b1));
}
__device__ __forceinline__ void cp16(uint32_t dst, const void* src) {
    asm volatile("cp.async.cg.shared.global [%0], [%1], 16;" :: "r"(dst), "l"(src));
}
#define CP_COMMIT() asm volatile("cp.async.commit_group;" ::: "memory")
#define CP_WAIT(n)  asm volatile("cp.async.wait_group %0;" :: "n"(n) : "memory")

__device__ __forceinline__ float ex2(float x) {
    float y;
    asm("ex2.approx.ftz.f32 %0, %1;" : "=f"(y) : "f"(x));
    return y;
}

// online-softmax merge, log2 domain
__device__ __forceinline__ void comb2(float& m, float& s, float m2, float s2) {
    float M = fmaxf(m, m2);
    float S;
    if (M == -INFINITY) S = 0.f;
    else S = ((m  == -INFINITY) ? 0.f : s  * ex2(m  - M))
           + ((m2 == -INFINITY) ? 0.f : s2 * ex2(m2 - M));
    m = M; s = S;
}

// cp.async nrows x 128 bf16 rows into padded smem (16B chunks, 16 per row)
__device__ __forceinline__ void cp_rows(const __nv_bfloat16* __restrict__ src, int rowBase,
                                        uint32_t dstBase, int tid, int nthr, int nrows) {
    for (int i = tid; i < nrows * 16; i += nthr) {
        int row = i >> 4, c = i & 15;
        cp16(dstBase + row * PKB + c * 16, src + (size_t)(rowBase + row) * D + c * 8);
    }
}

// ---------------------------------------------------------------------------
// Kernel 0: zero sums/counters + detect label word width.
// ---------------------------------------------------------------------------
__global__ void init_detect_k(const int* __restrict__ lw) {
    int t = threadIdx.x;
    if (t < 2 * D) ((float*)g_G)[t] = 0.0f;
    if (t < 2)     g_C[t] = 0;
    if (t == 2)    g_fin_count = 0;
    if (t == 3)    g_ready = 0;
    int local = 0;
    for (int i = 1 + 2 * t; i < N_TOT; i += 2 * 256) local |= lw[i];
    __shared__ int anynz;
    if (t == 0) anynz = 0;
    __syncthreads();
    if (local) atomicOr(&anynz, 1);
    __syncthreads();
    if (t == 0) g_is64 = anynz ? 0 : 1;
}

// ---------------------------------------------------------------------------
// Kernel 1: FUSED convert + pure-bf16 GEMM + online logsumexp.
// Phase 0: each of the 608 co-resident CTAs converts its ~14-row slice
// (bf16 + exact norms + cls + per-class G/C) and inits its slot slice, then
// spin-barriers on a global counter (deadlock-free: 1 wave, 4 CTAs/SM).
// Phase 1: GEMM identical to R12/R13 (protected win); partials now written
// to the transposed float2 layout.
// ---------------------------------------------------------------------------
__global__ void __launch_bounds__(128, 4) lse_mma_k(const float* __restrict__ f,
                                                    const int* __restrict__ lw) {
    extern __shared__ char smc[];
    const uint32_t base = smem_u32(smc);

    const int tid  = threadIdx.x;
    const int wid  = tid >> 5;
    const int lane = tid & 31;
    const int wrow = wid * 32;
    const int lrow = (lane & 7) + ((lane >> 3) & 1) * 8;
    const int lkof = (lane >> 4) * 16;
    const int c    = blockIdx.x;

    // ================= phase 0: convert slice + prep + slot init ==========
    {
        __shared__ float sG[2 * D];
        __shared__ int   sC[2];
        sG[tid] = 0.f; sG[tid + 128] = 0.f;
        if (tid < 2) sC[tid] = 0;
        __syncthreads();

        const int rs = (c * N_TOT) / NCTA;
        const int re = ((c + 1) * N_TOT) / NCTA;   // 13-14 rows
        const int is64 = g_is64;

        for (int r = rs + wid; r < re; r += 4) {
            float4 v = ((const float4*)(f + (size_t)r * D))[lane];
            __nv_bfloat16 hx = __float2bfloat16(v.x);
            __nv_bfloat16 hy = __float2bfloat16(v.y);
            __nv_bfloat16 hz = __float2bfloat16(v.z);
            __nv_bfloat16 hw = __float2bfloat16(v.w);
            __nv_bfloat162 hp0 = __halves2bfloat162(hx, hy);
            __nv_bfloat162 hp1 = __halves2bfloat162(hz, hw);
            uint2 H;
            H.x = *reinterpret_cast<uint32_t*>(&hp0);
            H.y = *reinterpret_cast<uint32_t*>(&hp1);
            *(uint2*)(g_hi + (size_t)r * D + lane * 4) = H;

            float sq = v.x * v.x + v.y * v.y + v.z * v.z + v.w * v.w;
            #pragma unroll
            for (int off = 16; off > 0; off >>= 1)
                sq += __shfl_xor_sync(0xffffffffu, sq, off);

            uint32_t bal = __ballot_sync(0xffffffffu,
                (v.x != 0.f) || (v.y != 0.f) || (v.z != 0.f) || (v.w != 0.f));
            int lab = is64 ? lw[2 * r] : lw[r];
            int cls = bal ? (lab + 1) : 0;
            if (lane == 0) {
                g_cls[r]  = cls;
                g_norm[r] = sq;
            }
            if (cls) {
                float* dst = sG + (cls - 1) * D + lane * 4;
                atomicAdd(dst + 0, v.x);
                atomicAdd(dst + 1, v.y);
                atomicAdd(dst + 2, v.z);
                atomicAdd(dst + 3, v.w);
                if (lane == 0) atomicAdd(&sC[cls - 1], 1);
            }
        }
        __syncthreads();
        atomicAdd(&((float*)g_G)[tid],       sG[tid]);
        atomicAdd(&((float*)g_G)[tid + 128], sG[tid + 128]);
        if (tid < 2) atomicAdd(&g_C[tid], sC[tid]);

        // slot init: this CTA's slice of the N_TOT*NSLOT float2 array
        float2* pp = &g_pp[0][0];
        const int e0 = (c * (N_TOT * NSLOT)) / NCTA;
        const int e1 = ((c + 1) * (N_TOT * NSLOT)) / NCTA;
        for (int i = e0 + tid; i < e1; i += 128)
            pp[i] = make_float2(-INFINITY, 0.f);

        // release + arrive + spin (all 608 CTAs resident -> safe)
        __syncthreads();
        __threadfence();
        if (tid == 0) {
            atomicAdd(&g_ready, 1);
            while (*(volatile int*)&g_ready < NCTA) { }
        }
        __syncthreads();
        __threadfence();
    }

    // ================= phase 1: GEMM + fused LSE ==========================
    const int u0 = (c * NUNITS) / NCTA;
    const int u1 = ((c + 1) * NUNITS) / NCTA;

    int nseg, sI[2], sA[2], sB[2];
    {
        int I0 = u0 >> 5, bnd = (I0 + 1) << 5;
        int e1 = (u1 < bnd) ? u1 : bnd;
        sI[0] = I0;
        sA[0] = (u0 & 31) * 8;
        sB[0] = sA[0] + (e1 - u0) * 8;
        if (u1 > bnd) { sI[1] = I0 + 1; sA[1] = 0; sB[1] = (u1 - bnd) * 8; nseg = 2; }
        else nseg = 1;
    }
    const int slot = c & (NSLOT - 1);

    const uint32_t aB = base + OFF_A + (wrow + lrow) * PKB + lkof;

    for (int g = 0; g < nseg; g++) {
        const int rowI = sI[g] * 128;
        const int jA = sA[g], jB = sB[g];

        cp_rows(g_hi, rowI, base + OFF_A, tid, 128, 128);
        cp_rows(g_hi, jA * 32, base + OFF_B(0), tid, 128, 32);
        CP_COMMIT();

        float mrun[4], srun[4];
        #pragma unroll
        for (int i = 0; i < 4; i++) { mrun[i] = 0.f; srun[i] = 0.f; }

        for (int s = jA; s < jB; s++) {
            const int p = (s - jA) & 1, q = p ^ 1;

            CP_WAIT(0);
            __syncthreads();

            if (s + 1 < jB) {
                cp_rows(g_hi, (s + 1) * 32, base + OFF_B(q), tid, 128, 32);
                CP_COMMIT();
            }

            float acc[2][4][4];
            #pragma unroll
            for (int mb = 0; mb < 2; mb++)
                #pragma unroll
                for (int nt = 0; nt < 4; nt++)
                    #pragma unroll
                    for (int cc = 0; cc < 4; cc++) acc[mb][nt][cc] = 0.f;

            const uint32_t bB = base + OFF_B(p) + lrow * PKB + lkof;

            #pragma unroll
            for (int ks = 0; ks < 8; ks++) {
                uint32_t aH[2][4];
                ldsm4(aH[0], aB + ks * 32);
                ldsm4(aH[1], aB + 16 * PKB + ks * 32);
                #pragma unroll
                for (int np = 0; np < 2; np++) {
                    uint32_t bH[4];
                    ldsm4(bH, bB + np * (16 * PKB) + ks * 32);
                    #pragma unroll
                    for (int mb = 0; mb < 2; mb++) {
                        mma16816(acc[mb][np * 2 + 0], aH[mb], bH[0], bH[2]);
                        mma16816(acc[mb][np * 2 + 1], aH[mb], bH[1], bH[3]);
                    }
                }
            }

            if (s * 32 == rowI + wrow) {   // exclude exact diagonal
                #pragma unroll
                for (int mb = 0; mb < 2; mb++)
                    #pragma unroll
                    for (int nt = 0; nt < 4; nt++)
                        #pragma unroll
                        for (int cc = 0; cc < 4; cc++) {
                            int rl = mb * 16 + ((cc >> 1) << 3) + (lane >> 2);
                            int cl = nt * 8 + ((lane & 3) << 1) + (cc & 1);
                            if (rl == cl) acc[mb][nt][cc] = -INFINITY;
                        }
            }

            #pragma unroll
            for (int mb = 0; mb < 2; mb++) {
                float tm0 = -INFINITY, tm1 = -INFINITY;
                #pragma unroll
                for (int nt = 0; nt < 4; nt++) {
                    tm0 = fmaxf(tm0, fmaxf(acc[mb][nt][0], acc[mb][nt][1]));
                    tm1 = fmaxf(tm1, fmaxf(acc[mb][nt][2], acc[mb][nt][3]));
                }
                float ts0 = tm0 * SCALE_LOG2, ts1 = tm1 * SCALE_LOG2;
                int i0 = mb * 2, i1 = i0 + 1;
                if (ts0 > mrun[i0]) { srun[i0] *= ex2(mrun[i0] - ts0); mrun[i0] = ts0; }
                if (ts0 >= mrun[i0] - 64.0f) {
                    float a0 = 0.f, a1 = 0.f;
                    #pragma unroll
                    for (int nt = 0; nt < 4; nt++) {
                        a0 += ex2(fmaf(acc[mb][nt][0], SCALE_LOG2, -mrun[i0]));
                        a1 += ex2(fmaf(acc[mb][nt][1], SCALE_LOG2, -mrun[i0]));
                    }
                    srun[i0] += a0 + a1;
                }
                if (ts1 > mrun[i1]) { srun[i1] *= ex2(mrun[i1] - ts1); mrun[i1] = ts1; }
                if (ts1 >= mrun[i1] - 64.0f) {
                    float b0 = 0.f, b1 = 0.f;
                    #pragma unroll
                    for (int nt = 0; nt < 4; nt++) {
                        b0 += ex2(fmaf(acc[mb][nt][2], SCALE_LOG2, -mrun[i1]));
                        b1 += ex2(fmaf(acc[mb][nt][3], SCALE_LOG2, -mrun[i1]));
                    }
                    srun[i1] += b0 + b1;
                }
            }
        }

        #pragma unroll
        for (int i = 0; i < 4; i++) {
            #pragma unroll
            for (int off = 1; off <= 2; off <<= 1) {
                float mm = __shfl_xor_sync(0xffffffffu, mrun[i], off);
                float ss = __shfl_xor_sync(0xffffffffu, srun[i], off);
                comb2(mrun[i], srun[i], mm, ss);
            }
        }
        if ((lane & 3) == 0) {
            int r0 = rowI + wrow + (lane >> 2);
            g_pp[r0][slot]      = make_float2(mrun[0], srun[0]);
            g_pp[r0 + 8][slot]  = make_float2(mrun[1], srun[1]);
            g_pp[r0 + 16][slot] = make_float2(mrun[2], srun[2]);
            g_pp[r0 + 24][slot] = make_float2(mrun[3], srun[3]);
        }
        __syncthreads();
    }
}

// ---------------------------------------------------------------------------
// Kernel 2: per-anchor finalize + fused final reduction (last block).
// 256 blocks x 256 threads; 8 threads/anchor; partials now coalesced float2.
// ---------------------------------------------------------------------------
__global__ void fin_k(const float* __restrict__ f, float* __restrict__ out) {
    __shared__ float Gs[2 * D];
    __shared__ float red[32];
    __shared__ int   lastFlag;
    const int t = threadIdx.x;
    Gs[t] = ((const float*)g_G)[t];
    __syncthreads();

    const int aIdx = t >> 3;                 // 32 anchors per block
    const int ot   = t & 7;                  // octet thread
    const int i    = blockIdx.x * 32 + aIdx;

    int cls = g_cls[i];

    // combine 2 slots per thread (coalesced: 16 float2 contiguous per anchor)
    float2 p0 = g_pp[i][ot];
    float2 p1 = g_pp[i][ot + 8];
    float M = p0.x, S = p0.y;
    comb2(M, S, p1.x, p1.y);

    // 16-element dot slice
    float dot = 0.f;
    {
        int lab = (cls == 2) ? 1 : 0;
        const float4* fr = (const float4*)(f + (size_t)i * D) + ot * 4;
        const float4* gr = (const float4*)(Gs + lab * D) + ot * 4;
        #pragma unroll
        for (int k = 0; k < 4; k++) {
            float4 a = fr[k]; float4 g = gr[k];
            dot = fmaf(a.x, g.x, dot); dot = fmaf(a.y, g.y, dot);
            dot = fmaf(a.z, g.z, dot); dot = fmaf(a.w, g.w, dot);
        }
    }

    // octet butterfly
    #pragma unroll
    for (int off = 1; off <= 4; off <<= 1) {
        float mm = __shfl_xor_sync(0xffffffffu, M, off);
        float ss = __shfl_xor_sync(0xffffffffu, S, off);
        comb2(M, S, mm, ss);
        dot += __shfl_xor_sync(0xffffffffu, dot, off);
    }

    float term = 0.f;
    if (ot == 0 && cls != 0) {
        comb2(M, S, g_norm[i] * SCALE_LOG2, 1.0f);   // exact diagonal
        float lse = (M + log2f(S)) * LN2F;
        float cnt = (float)g_C[(cls == 2) ? 1 : 0];
        term = (cnt * lse - dot * TEMP_INV) * (1.0f / 128.0f);
    }

    if (ot == 0) red[aIdx] = term;
    __syncthreads();
    if (t < 32) {
        float v = red[t];
        #pragma unroll
        for (int off = 16; off > 0; off >>= 1)
            v += __shfl_xor_sync(0xffffffffu, v, off);
        if (t == 0) {
            g_bsum[blockIdx.x] = v;
            __threadfence();
            int old = atomicAdd(&g_fin_count, 1);
            lastFlag = (old == FIN_BLOCKS - 1);
        }
    }
    __syncthreads();

    if (lastFlag && t < 32) {
        float v = 0.f;
        #pragma unroll
        for (int k = 0; k < FIN_BLOCKS / 32; k++)
            v += g_bsum[t + k * 32];
        #pragma unroll
        for (int off = 16; off > 0; off >>= 1)
            v += __shfl_xor_sync(0xffffffffu, v, off);
        if (t == 0) out[0] = v * (1.0f / 256.0f);
    }
}

// ---------------------------------------------------------------------------
extern "C" void kernel_launch(void* const* d_in, const int* in_sizes, int n_in,
                              void* d_out, int out_size) {
    const float* f  = (const float*)d_in[0];
    const int*   lw = (const int*)d_in[1];
    float* out = (float*)d_out;

    cudaFuncSetAttribute(lse_mma_k, cudaFuncAttributeMaxDynamicSharedMemorySize, SMEM_BYTES);

    init_detect_k<<<1, 256>>>(lw);
    lse_mma_k<<<NCTA, 128, SMEM_BYTES>>>(f, lw);
    fin_k<<<FIN_BLOCKS, 256>>>(f, out);
}